// round 14
// baseline (speedup 1.0000x reference)
#include <cuda_runtime.h>
#include <cstdint>
#include <math.h>

#define EPSV 1e-5f

// ---------------- scratch (no allocation allowed) ----------------
__device__ float g_a[4*48*64*64];
__device__ float g_b[4*48*64*64];
__device__ float g_p64[4*4*48*64*64];   // 4 split-K slices, 64^2 convs
__device__ float g_c[4*48*32*32];
__device__ float g_d[4*48*32*32];
__device__ float g_p32[8*4*48*32*32];   // 8 split-K slices, 32^2 convs
__device__ float g_skp[2*4*9*32*32];    // 2 split-K slices, skernel conv

// ---------------- cp.async helpers ----------------
__device__ __forceinline__ uint32_t s2u(const void* p) {
    return (uint32_t)__cvta_generic_to_shared(p);
}
__device__ __forceinline__ void cp4(uint32_t dst, const float* src) {
    asm volatile("cp.async.ca.shared.global [%0], [%1], 4;\n"
                 :: "r"(dst), "l"(src));
}
__device__ __forceinline__ void cp16(uint32_t dst, const float* src) {
    asm volatile("cp.async.ca.shared.global [%0], [%1], 16;\n"
                 :: "r"(dst), "l"(src));
}
#define CP_COMMIT() asm volatile("cp.async.commit_group;\n" ::: "memory")
#define CP_WAIT1()  asm volatile("cp.async.wait_group 1;\n" ::: "memory")

// ---------------- x1 = x_[:, :, ::4, ::4] ----------------
__global__ void down_kernel(const float* __restrict__ xs, float* __restrict__ out) {
    int i = blockIdx.x * blockDim.x + threadIdx.x;
    if (i >= 4*48*64*64) return;
    int w  = i & 63;
    int t  = i >> 6;
    int h  = t & 63;
    int nc = t >> 6;
    out[i] = xs[((size_t)nc * 256 + (size_t)h * 4) * 256 + (size_t)w * 4];
}

// ---------------- block-wide (sum, sumsq) reduction, NT threads ----------------
template<int NT>
__device__ __forceinline__ void blk_stats(float lsum, float lsq, float* sred, int tid,
                                          float inv, float& mean, float& var) {
    constexpr int NW = NT / 32;
    __syncthreads();
    #pragma unroll
    for (int o = 16; o; o >>= 1) {
        lsum += __shfl_xor_sync(0xffffffffu, lsum, o);
        lsq  += __shfl_xor_sync(0xffffffffu, lsq,  o);
    }
    if ((tid & 31) == 0) { sred[tid >> 5] = lsum; sred[NW + (tid >> 5)] = lsq; }
    __syncthreads();
    if (tid < 32) {
        float a = (tid < NW) ? sred[tid]      : 0.f;
        float b = (tid < NW) ? sred[NW + tid] : 0.f;
        #pragma unroll
        for (int o = 16; o; o >>= 1) {
            a += __shfl_xor_sync(0xffffffffu, a, o);
            b += __shfl_xor_sync(0xffffffffu, b, o);
        }
        if (tid == 0) { sred[2 * NW] = a; sred[2 * NW + 1] = b; }
    }
    __syncthreads();
    mean = sred[2 * NW] * inv;
    var  = sred[2 * NW + 1] * inv - mean * mean;
}

// ---------------- conv3x3 (48 -> COUT), full-width tiles, pair-stage pipeline ---
// Tile H x 16 (full width), 256 threads as 16x16, PX px/thread, KO couts/CTA.
// Row-wise window compute (6-reg window) so 4 CTAs/SM fit at 64 regs.
// smem row: data at float cols [4, H+4), zeros elsewhere (SAME pad via one-time
// zero fill; out-of-range rows never written).
// TWO input channels per pipeline stage; 6 buffers (3 pairs), prefetch 1 pair.
// Writes split-K partials; consumer adds bias + merges.
template<int H, int PX, int COUT, int KO, int SPLIT>
__global__ void __launch_bounds__(256, 4)
conv_fast(const float* __restrict__ in, float* __restrict__ out,
          const float* __restrict__ W) {
    constexpr int TH = 16, SROW = H + 8;
    constexpr int CN   = 48 / SPLIT;           // even
    constexpr int NV   = H / 4;                // float4s per row
    constexpr int NOPS = (TH + 2) * NV;        // cp16 ops per tile
    constexpr int NLD  = (NOPS + 255) / 256;
    constexpr int BUFSZ = (TH + 2) * SROW;

    __shared__ __align__(16) float s_t[6][BUFSZ];
    __shared__ __align__(16) float s_w[CN * 9 * KO];

    const int tid = threadIdx.x;
    const int tx  = tid & 15, ty = tid >> 4;
    const int tile = blockIdx.x, g = blockIdx.y;
    const int n  = blockIdx.z / SPLIT, sp = blockIdx.z % SPLIT;
    const int ci0 = sp * CN;
    const int ty0 = tile * TH;

    // one-time zero fill (halo cols + out-of-range rows stay 0 forever)
    for (int i = tid; i < 6 * BUFSZ; i += 256) ((float*)s_t)[i] = 0.f;

    // stage weights transposed: s_w[(ci*9+k)*KO + ko]
    for (int i = tid; i < CN * 9 * KO; i += 256) {
        int ko = i % KO;
        int rest = i / KO;
        int k = rest % 9, ci = rest / 9;
        s_w[i] = W[(((size_t)(g * KO + ko)) * 48 + ci0 + ci) * 9 + k];
    }

    // precompute tile-load slots (float4 rows; reused every channel)
    const float* inb = in + ((size_t)n * 48 + ci0) * H * H;
    int goff[NLD], soff[NLD]; bool act[NLD];
    #pragma unroll
    for (int j = 0; j < NLD; j++) {
        int e = tid + j * 256;
        int r = e / NV, q = e - r * NV;
        int gr = ty0 + r - 1;
        act[j]  = (e < NOPS) && (unsigned)gr < (unsigned)H;
        goff[j] = act[j] ? gr * H + q * 4 : 0;
        soff[j] = r * SROW + 4 + q * 4;
    }
    uint32_t sb[6];
    #pragma unroll
    for (int b = 0; b < 6; b++) sb[b] = s2u(s_t[b]);

    auto ldtile = [&](int ci, int b) {
        const float* ch = inb + (size_t)ci * H * H;
        #pragma unroll
        for (int j = 0; j < NLD; j++)
            if (act[j]) cp16(sb[b] + (uint32_t)soff[j] * 4, ch + goff[j]);
    };

    float acc[KO][PX];
    #pragma unroll
    for (int ko = 0; ko < KO; ko++)
        #pragma unroll
        for (int p = 0; p < PX; p++) acc[ko][p] = 0.f;

    // row-wise window compute: one 6-reg window row live at a time
    auto compute_ci = [&](const float* buf, int ci) {
        #pragma unroll
        for (int dy = 0; dy < 3; dy++) {
            float win[PX + 2];
            const float* rp = &buf[(ty + dy) * SROW + tx * PX + 3];
            if (PX == 4) {
                win[0] = rp[0];
                float4 a = *(const float4*)(rp + 1);     // 16B aligned
                win[1] = a.x; win[2] = a.y; win[3] = a.z; win[4] = a.w;
                win[5] = rp[5];
            } else {
                win[0] = rp[0];
                float2 a = *(const float2*)(rp + 1);     // 8B aligned
                win[1] = a.x; win[2] = a.y;
                win[3] = rp[3];
            }
            #pragma unroll
            for (int dx = 0; dx < 3; dx++) {
                float wv[KO];
                if (KO == 8) {
                    float4 w4 = *(const float4*)&s_w[(ci * 9 + dy * 3 + dx) * 8];
                    float4 w5 = *(const float4*)&s_w[(ci * 9 + dy * 3 + dx) * 8 + 4];
                    wv[0] = w4.x; wv[1] = w4.y; wv[2] = w4.z; wv[3] = w4.w;
                    wv[4] = w5.x; wv[5] = w5.y; wv[6] = w5.z; wv[7] = w5.w;
                } else if (KO == 4) {
                    float4 w4 = *(const float4*)&s_w[(ci * 9 + dy * 3 + dx) * 4];
                    wv[0] = w4.x; wv[1] = w4.y; wv[2] = w4.z; wv[3] = w4.w;
                } else {
                    #pragma unroll
                    for (int ko = 0; ko < KO; ko++)
                        wv[ko] = s_w[(ci * 9 + dy * 3 + dx) * KO + ko];
                }
                #pragma unroll
                for (int ko = 0; ko < KO; ko++)
                    #pragma unroll
                    for (int p = 0; p < PX; p++)
                        acc[ko][p] = fmaf(win[dx + p], wv[ko], acc[ko][p]);
            }
        }
    };

    __syncthreads();      // zero-fill + s_w visible before first cp.async
    ldtile(0, 0);
    ldtile(1, 1);
    CP_COMMIT();          // pair 0

    for (int p = 0; p < CN / 2; p++) {
        const int ci = 2 * p;
        const int nb = ((p + 1) % 3) * 2;
        if (ci + 2 < CN) { ldtile(ci + 2, nb); ldtile(ci + 3, nb + 1); }
        CP_COMMIT();      // pair p+1 (possibly empty)
        CP_WAIT1();       // pair p landed
        __syncthreads();
        const int cb = (p % 3) * 2;
        compute_ci(s_t[cb],     ci);
        compute_ci(s_t[cb + 1], ci + 1);
    }

    const int gy  = ty0 + ty;
    const int gxb = tx * PX;
    float* ob = out + (size_t)sp * 4 * COUT * H * H;
    #pragma unroll
    for (int ko = 0; ko < KO; ko++) {
        int co = g * KO + ko;
        float* dst = &ob[(((size_t)n * COUT + co) * H + gy) * H + gxb];
        if (PX == 4)
            *(float4*)dst = make_float4(acc[ko][0], acc[ko][1], acc[ko][2], acc[ko][3]);
        else
            *(float2*)dst = make_float2(acc[ko][0], acc[ko][1]);
    }
}

// ---------------- instance-norm tail (bias + merge NPART split-K partials) -------
// FULL: inorm, prelu, inorm, +residual.  !FULL: inorm, prelu.
// POOL: 2x2-maxpool via smem plane, store (H/2)^2.
template<int H, int NT, bool FULL, int NPART, bool POOL>
__global__ void __launch_bounds__(NT)
norm_kernel(const float* __restrict__ y, const float* __restrict__ B,
            const float* __restrict__ resid, float* __restrict__ out,
            const float* __restrict__ alpha_ptr) {
    constexpr int PX = H * H / NT;
    constexpr size_t PSTRIDE = (size_t)4 * 48 * H * H;
    constexpr int NW = NT / 32;
    __shared__ float sred[2 * NW + 2];
    __shared__ float s_plane[POOL ? H * H : 2];
    const int c = blockIdx.x, n = blockIdx.y, tid = threadIdx.x;
    const size_t base = ((size_t)n * 48 + c) * H * H;
    const float inv = 1.0f / (float)(H * H);
    const float b = B[c];

    float v[PX];
    float lsum = 0.f, lsq = 0.f;
    #pragma unroll
    for (int i = 0; i < PX; i++) {
        size_t idx = base + tid + i * NT;
        float t = b;
        #pragma unroll
        for (int p = 0; p < NPART; p++) t += y[p * PSTRIDE + idx];
        v[i] = t;
        lsum += t; lsq += t * t;
    }
    float m, va;
    blk_stats<NT>(lsum, lsq, sred, tid, inv, m, va);
    float rs = rsqrtf(va + EPSV);
    const float alpha = __ldg(alpha_ptr);

    lsum = 0.f; lsq = 0.f;
    #pragma unroll
    for (int i = 0; i < PX; i++) {
        float t = (v[i] - m) * rs;
        t = (t >= 0.f) ? t : alpha * t;
        v[i] = t;
        lsum += t; lsq += t * t;
    }

    if (!FULL) {
        #pragma unroll
        for (int i = 0; i < PX; i++) out[base + tid + i * NT] = v[i];
        return;
    }

    float m2, v2;
    blk_stats<NT>(lsum, lsq, sred, tid, inv, m2, v2);
    float rs2 = rsqrtf(v2 + EPSV);

    #pragma unroll
    for (int i = 0; i < PX; i++) {
        int px = tid + i * NT;
        float f = (v[i] - m2) * rs2 + resid[base + px];
        if (POOL) s_plane[px] = f;
        else      out[base + px] = f;
    }

    if (POOL) {
        __syncthreads();
        constexpr int HP = H / 2;
        const size_t ob = ((size_t)n * 48 + c) * HP * HP;
        #pragma unroll
        for (int j = 0; j < (HP * HP + NT - 1) / NT; j++) {
            int p = tid + j * NT;
            if (p < HP * HP) {
                int hh = p / HP, ww = p % HP;
                const float* q = &s_plane[(hh * 2) * H + ww * 2];
                out[ob + p] = fmaxf(fmaxf(q[0], q[1]), fmaxf(q[H], q[H + 1]));
            }
        }
    }
}

// ---------------- fused: bilinear-8x upsample + softmax + 3x3 reflect apply ----
// skernel arrives as 2 split-K partials + bias. Pair-stage pipeline, 6 buffers.
__global__ void __launch_bounds__(256)
apply_fused(const float* __restrict__ x, const float* __restrict__ sk,
            const float* __restrict__ kb2, float* __restrict__ out) {
    constexpr int SROW = 20, BUFSZ = 18 * SROW;
    __shared__ float s_t[6][BUFSZ];

    const int n   = blockIdx.z;
    const int tid = threadIdx.x;
    const int txx = tid & 15, tyy = tid >> 4;
    const int w0 = blockIdx.x * 16, h0 = blockIdx.y * 16;
    const int w = w0 + txx, h = h0 + tyy;

    // bilinear (align corners): src = o*31/255
    float fh = ((float)h * 31.0f) / 255.0f;
    int r0 = (int)floorf(fh);
    float fr = fh - (float)r0;
    int r1 = min(r0 + 1, 31);
    float fw = ((float)w * 31.0f) / 255.0f;
    int c0 = (int)floorf(fw);
    float fc = fw - (float)c0;
    int c1 = min(c0 + 1, 31);
    const float w00 = (1.f - fr) * (1.f - fc);
    const float w01 = (1.f - fr) * fc;
    const float w10 = fr * (1.f - fc);
    const float w11 = fr * fc;

    float kv[9];
    const float* skb = sk + (size_t)n * 9 * 1024;
    #pragma unroll
    for (int p = 0; p < 9; p++) {
        float a = 0.f;
        #pragma unroll
        for (int s = 0; s < 2; s++) {
            const float* sp = skb + (size_t)s * 4 * 9 * 1024 + p * 1024;
            a += w00 * __ldg(&sp[r0*32+c0]) + w01 * __ldg(&sp[r0*32+c1])
               + w10 * __ldg(&sp[r1*32+c0]) + w11 * __ldg(&sp[r1*32+c1]);
        }
        kv[p] = a + __ldg(&kb2[p]);
    }
    float mx = kv[0];
    #pragma unroll
    for (int p = 1; p < 9; p++) mx = fmaxf(mx, kv[p]);
    float sum = 0.f;
    #pragma unroll
    for (int p = 0; p < 9; p++) { kv[p] = __expf(kv[p] - mx); sum += kv[p]; }
    float is = 1.0f / sum;
    #pragma unroll
    for (int p = 0; p < 9; p++) kv[p] *= is;

    // precompute reflect-padded load slots (324 elems, <=2 per thread)
    int goff[2], soff[2]; bool act[2];
    #pragma unroll
    for (int j = 0; j < 2; j++) {
        int e = tid + j * 256;
        act[j] = (e < 324);
        int r = e / 18, cc = e - r * 18;
        int gr = h0 + r - 1; gr = gr < 0 ? -gr : (gr > 255 ? 510 - gr : gr);
        int gc = w0 + cc - 1; gc = gc < 0 ? -gc : (gc > 255 ? 510 - gc : gc);
        goff[j] = act[j] ? gr * 256 + gc : 0;
        soff[j] = act[j] ? r * SROW + cc : 0;
    }
    uint32_t sb[6];
    #pragma unroll
    for (int b = 0; b < 6; b++) sb[b] = s2u(s_t[b]);

    const float* xb = x + (size_t)n * 48 * 65536;
    float* ob = out + (size_t)n * 48 * 65536 + (size_t)h * 256 + w;

    auto ldch = [&](int c, int b) {
        const float* xc = xb + (size_t)c * 65536;
        #pragma unroll
        for (int j = 0; j < 2; j++)
            if (act[j]) cp4(sb[b] + (uint32_t)soff[j] * 4, xc + goff[j]);
    };

    ldch(0, 0);
    ldch(1, 1);
    CP_COMMIT();          // pair 0

    for (int p = 0; p < 24; p++) {
        const int c = 2 * p;
        const int nb = ((p + 1) % 3) * 2;
        if (c + 2 < 48) { ldch(c + 2, nb); ldch(c + 3, nb + 1); }
        CP_COMMIT();
        CP_WAIT1();
        __syncthreads();
        const int cb = (p % 3) * 2;
        #pragma unroll
        for (int q = 0; q < 2; q++) {
            const float* buf = s_t[cb + q];
            float s = 0.f;
            #pragma unroll
            for (int dy = 0; dy < 3; dy++)
                #pragma unroll
                for (int dx = 0; dx < 3; dx++)
                    s = fmaf(kv[dy * 3 + dx], buf[(tyy + dy) * SROW + txx + dx], s);
            ob[(size_t)(c + q) * 65536] = s;
        }
    }
}

// ---------------- host launcher ----------------
extern "C" void kernel_launch(void* const* d_in, const int* in_sizes, int n_in,
                              void* d_out, int out_size) {
    const float* x   = (const float*)d_in[0];
    const float* x_  = (const float*)d_in[1];
    const float* p1w = (const float*)d_in[2];
    const float* p1b = (const float*)d_in[3];
    const float* p1a = (const float*)d_in[4];
    const float* p2w = (const float*)d_in[5];
    const float* p2b = (const float*)d_in[6];
    const float* p2a = (const float*)d_in[7];
    const float* kw1 = (const float*)d_in[8];
    const float* kb1 = (const float*)d_in[9];
    const float* ka  = (const float*)d_in[10];
    const float* kw2 = (const float*)d_in[11];
    const float* kb2 = (const float*)d_in[12];
    float* out = (float*)d_out;

    float *ga, *gb, *gc, *gd, *gp64, *gp32, *gskp;
    cudaGetSymbolAddress((void**)&ga,   g_a);
    cudaGetSymbolAddress((void**)&gb,   g_b);
    cudaGetSymbolAddress((void**)&gc,   g_c);
    cudaGetSymbolAddress((void**)&gd,   g_d);
    cudaGetSymbolAddress((void**)&gp64, g_p64);
    cudaGetSymbolAddress((void**)&gp32, g_p32);
    cudaGetSymbolAddress((void**)&gskp, g_skp);

    const size_t WS = (size_t)48 * 48 * 9;
    const dim3 g64(4, 6, 16);     // 4 row-tiles, 6 cout-groups (KO=8), n*split4
    const dim3 g32(2, 6, 32);     // 2 row-tiles, 6 groups (KO=8), n*split8
    const dim3 gnorm(48, 4);

    // x1 = x_[:, :, ::4, ::4]
    down_kernel<<<(4*48*64*64 + 255) / 256, 256>>>(x_, ga);

    // 3 basic blocks @ 64x64 (split4 partials; merge+bias+resid in norm)
    conv_fast<64, 4, 48, 8, 4><<<g64, 256>>>(ga, gp64, p1w + 0 * WS);
    norm_kernel<64, 1024, true, 4, false><<<gnorm, 1024>>>(gp64, p1b + 0,  ga, gb, p1a + 0);
    conv_fast<64, 4, 48, 8, 4><<<g64, 256>>>(gb, gp64, p1w + 1 * WS);
    norm_kernel<64, 1024, true, 4, false><<<gnorm, 1024>>>(gp64, p1b + 48, gb, ga, p1a + 1);
    conv_fast<64, 4, 48, 8, 4><<<g64, 256>>>(ga, gp64, p1w + 2 * WS);
    // block-3 tail + fused 2x2 maxpool -> gc (32^2)
    norm_kernel<64, 1024, true, 4, true><<<gnorm, 1024>>>(gp64, p1b + 96, ga, gc, p1a + 2);

    // 3 basic blocks @ 32x32 (8-way ci-split, merged in norm)
    conv_fast<32, 2, 48, 8, 8><<<g32, 256>>>(gc, gp32, p2w + 0 * WS);
    norm_kernel<32, 256, true, 8, false><<<gnorm, 256>>>(gp32, p2b + 0,  gc, gd, p2a + 0);
    conv_fast<32, 2, 48, 8, 8><<<g32, 256>>>(gd, gp32, p2w + 1 * WS);
    norm_kernel<32, 256, true, 8, false><<<gnorm, 256>>>(gp32, p2b + 48, gd, gc, p2a + 1);
    conv_fast<32, 2, 48, 8, 8><<<g32, 256>>>(gc, gp32, p2w + 2 * WS);
    norm_kernel<32, 256, true, 8, false><<<gnorm, 256>>>(gp32, p2b + 96, gc, gd, p2a + 2);

    // head: conv + inorm + prelu
    conv_fast<32, 2, 48, 8, 8><<<g32, 256>>>(gd, gp32, kw1);
    norm_kernel<32, 256, false, 8, false><<<gnorm, 256>>>(gp32, kb1, nullptr, gc, ka);

    // skernel conv (9 couts, 2 split-K partials; bias added in apply)
    conv_fast<32, 2, 9, 3, 2><<<dim3(2, 3, 8), 256>>>(gc, gskp, kw2);

    // fused upsample + softmax + adaptive 3x3 apply
    apply_fused<<<dim3(16, 16, 4), 256>>>(x, gskp, kb2, out);
}

// round 16
// speedup vs baseline: 1.0829x; 1.0829x over previous
#include <cuda_runtime.h>
#include <cstdint>
#include <math.h>

#define EPSV 1e-5f

// ---------------- scratch (no allocation allowed) ----------------
__device__ float g_a[4*48*64*64];
__device__ float g_b[4*48*64*64];
__device__ float g_p64[8*4*48*64*64];   // 8 split-K slices, 64^2 convs
__device__ float g_c[4*48*32*32];
__device__ float g_d[4*48*32*32];
__device__ float g_p32[8*4*48*32*32];   // 8 split-K slices, 32^2 convs
__device__ float g_skp[2*4*9*32*32];    // 2 split-K slices, skernel conv

// ---------------- cp.async helpers ----------------
__device__ __forceinline__ uint32_t s2u(const void* p) {
    return (uint32_t)__cvta_generic_to_shared(p);
}
__device__ __forceinline__ void cp4(uint32_t dst, const float* src) {
    asm volatile("cp.async.ca.shared.global [%0], [%1], 4;\n"
                 :: "r"(dst), "l"(src));
}
__device__ __forceinline__ void cp16(uint32_t dst, const float* src) {
    asm volatile("cp.async.ca.shared.global [%0], [%1], 16;\n"
                 :: "r"(dst), "l"(src));
}
#define CP_COMMIT() asm volatile("cp.async.commit_group;\n" ::: "memory")
#define CP_WAIT1()  asm volatile("cp.async.wait_group 1;\n" ::: "memory")

// ---------------- x1 = x_[:, :, ::4, ::4] ----------------
__global__ void down_kernel(const float* __restrict__ xs, float* __restrict__ out) {
    int i = blockIdx.x * blockDim.x + threadIdx.x;
    if (i >= 4*48*64*64) return;
    int w  = i & 63;
    int t  = i >> 6;
    int h  = t & 63;
    int nc = t >> 6;
    out[i] = xs[((size_t)nc * 256 + (size_t)h * 4) * 256 + (size_t)w * 4];
}

// ---------------- block-wide (sum, sumsq) reduction, NT threads ----------------
template<int NT>
__device__ __forceinline__ void blk_stats(float lsum, float lsq, float* sred, int tid,
                                          float inv, float& mean, float& var) {
    constexpr int NW = NT / 32;
    __syncthreads();
    #pragma unroll
    for (int o = 16; o; o >>= 1) {
        lsum += __shfl_xor_sync(0xffffffffu, lsum, o);
        lsq  += __shfl_xor_sync(0xffffffffu, lsq,  o);
    }
    if ((tid & 31) == 0) { sred[tid >> 5] = lsum; sred[NW + (tid >> 5)] = lsq; }
    __syncthreads();
    if (tid < 32) {
        float a = (tid < NW) ? sred[tid]      : 0.f;
        float b = (tid < NW) ? sred[NW + tid] : 0.f;
        #pragma unroll
        for (int o = 16; o; o >>= 1) {
            a += __shfl_xor_sync(0xffffffffu, a, o);
            b += __shfl_xor_sync(0xffffffffu, b, o);
        }
        if (tid == 0) { sred[2 * NW] = a; sred[2 * NW + 1] = b; }
    }
    __syncthreads();
    mean = sred[2 * NW] * inv;
    var  = sred[2 * NW + 1] * inv - mean * mean;
}

// ---------------- conv3x3 (48 -> COUT), full-width tiles, pair-stage pipeline ---
// Tile H x 16 (full width), 256 threads as 16x16, PX px/thread, KO couts/CTA.
// Row-wise window compute (6-reg window) so 4 CTAs/SM fit at 64 regs.
// smem row: data at float cols [4, H+4), zeros elsewhere (SAME pad via one-time
// zero fill; out-of-range rows never written).
// TWO input channels per pipeline stage; 6 buffers (3 pairs), prefetch 1 pair.
// Writes split-K partials; consumer adds bias + merges.
template<int H, int PX, int COUT, int KO, int SPLIT>
__global__ void __launch_bounds__(256, 4)
conv_fast(const float* __restrict__ in, float* __restrict__ out,
          const float* __restrict__ W) {
    constexpr int TH = 16, SROW = H + 8;
    constexpr int CN   = 48 / SPLIT;           // even
    constexpr int NV   = H / 4;                // float4s per row
    constexpr int NOPS = (TH + 2) * NV;        // cp16 ops per tile
    constexpr int NLD  = (NOPS + 255) / 256;
    constexpr int BUFSZ = (TH + 2) * SROW;

    __shared__ __align__(16) float s_t[6][BUFSZ];
    __shared__ __align__(16) float s_w[CN * 9 * KO];

    const int tid = threadIdx.x;
    const int tx  = tid & 15, ty = tid >> 4;
    const int tile = blockIdx.x, g = blockIdx.y;
    const int n  = blockIdx.z / SPLIT, sp = blockIdx.z % SPLIT;
    const int ci0 = sp * CN;
    const int ty0 = tile * TH;

    // one-time zero fill (halo cols + out-of-range rows stay 0 forever)
    for (int i = tid; i < 6 * BUFSZ; i += 256) ((float*)s_t)[i] = 0.f;

    // stage weights transposed: s_w[(ci*9+k)*KO + ko]
    for (int i = tid; i < CN * 9 * KO; i += 256) {
        int ko = i % KO;
        int rest = i / KO;
        int k = rest % 9, ci = rest / 9;
        s_w[i] = W[(((size_t)(g * KO + ko)) * 48 + ci0 + ci) * 9 + k];
    }

    // precompute tile-load slots (float4 rows; reused every channel)
    const float* inb = in + ((size_t)n * 48 + ci0) * H * H;
    int goff[NLD], soff[NLD]; bool act[NLD];
    #pragma unroll
    for (int j = 0; j < NLD; j++) {
        int e = tid + j * 256;
        int r = e / NV, q = e - r * NV;
        int gr = ty0 + r - 1;
        act[j]  = (e < NOPS) && (unsigned)gr < (unsigned)H;
        goff[j] = act[j] ? gr * H + q * 4 : 0;
        soff[j] = r * SROW + 4 + q * 4;
    }
    uint32_t sb[6];
    #pragma unroll
    for (int b = 0; b < 6; b++) sb[b] = s2u(s_t[b]);

    auto ldtile = [&](int ci, int b) {
        const float* ch = inb + (size_t)ci * H * H;
        #pragma unroll
        for (int j = 0; j < NLD; j++)
            if (act[j]) cp16(sb[b] + (uint32_t)soff[j] * 4, ch + goff[j]);
    };

    float acc[KO][PX];
    #pragma unroll
    for (int ko = 0; ko < KO; ko++)
        #pragma unroll
        for (int p = 0; p < PX; p++) acc[ko][p] = 0.f;

    // row-wise window compute: one 6-reg window row live at a time
    auto compute_ci = [&](const float* buf, int ci) {
        #pragma unroll
        for (int dy = 0; dy < 3; dy++) {
            float win[PX + 2];
            const float* rp = &buf[(ty + dy) * SROW + tx * PX + 3];
            if (PX == 4) {
                win[0] = rp[0];
                float4 a = *(const float4*)(rp + 1);     // 16B aligned
                win[1] = a.x; win[2] = a.y; win[3] = a.z; win[4] = a.w;
                win[5] = rp[5];
            } else {
                win[0] = rp[0];
                float2 a = *(const float2*)(rp + 1);     // 8B aligned
                win[1] = a.x; win[2] = a.y;
                win[3] = rp[3];
            }
            #pragma unroll
            for (int dx = 0; dx < 3; dx++) {
                float wv[KO];
                if (KO == 8) {
                    float4 w4 = *(const float4*)&s_w[(ci * 9 + dy * 3 + dx) * 8];
                    float4 w5 = *(const float4*)&s_w[(ci * 9 + dy * 3 + dx) * 8 + 4];
                    wv[0] = w4.x; wv[1] = w4.y; wv[2] = w4.z; wv[3] = w4.w;
                    wv[4] = w5.x; wv[5] = w5.y; wv[6] = w5.z; wv[7] = w5.w;
                } else if (KO == 4) {
                    float4 w4 = *(const float4*)&s_w[(ci * 9 + dy * 3 + dx) * 4];
                    wv[0] = w4.x; wv[1] = w4.y; wv[2] = w4.z; wv[3] = w4.w;
                } else {
                    #pragma unroll
                    for (int ko = 0; ko < KO; ko++)
                        wv[ko] = s_w[(ci * 9 + dy * 3 + dx) * KO + ko];
                }
                #pragma unroll
                for (int ko = 0; ko < KO; ko++)
                    #pragma unroll
                    for (int p = 0; p < PX; p++)
                        acc[ko][p] = fmaf(win[dx + p], wv[ko], acc[ko][p]);
            }
        }
    };

    __syncthreads();      // zero-fill + s_w visible before first cp.async
    ldtile(0, 0);
    ldtile(1, 1);
    CP_COMMIT();          // pair 0

    for (int p = 0; p < CN / 2; p++) {
        const int ci = 2 * p;
        const int nb = ((p + 1) % 3) * 2;
        if (ci + 2 < CN) { ldtile(ci + 2, nb); ldtile(ci + 3, nb + 1); }
        CP_COMMIT();      // pair p+1 (possibly empty)
        CP_WAIT1();       // pair p landed
        __syncthreads();
        const int cb = (p % 3) * 2;
        compute_ci(s_t[cb],     ci);
        compute_ci(s_t[cb + 1], ci + 1);
    }

    const int gy  = ty0 + ty;
    const int gxb = tx * PX;
    float* ob = out + (size_t)sp * 4 * COUT * H * H;
    #pragma unroll
    for (int ko = 0; ko < KO; ko++) {
        int co = g * KO + ko;
        float* dst = &ob[(((size_t)n * COUT + co) * H + gy) * H + gxb];
        if (PX == 4)
            *(float4*)dst = make_float4(acc[ko][0], acc[ko][1], acc[ko][2], acc[ko][3]);
        else
            *(float2*)dst = make_float2(acc[ko][0], acc[ko][1]);
    }
}

// ---------------- instance-norm tail (bias + merge NPART split-K partials) -------
// FULL: inorm, prelu, inorm, +residual.  !FULL: inorm, prelu.
// POOL: 2x2-maxpool via smem plane, store (H/2)^2.
template<int H, int NT, bool FULL, int NPART, bool POOL>
__global__ void __launch_bounds__(NT)
norm_kernel(const float* __restrict__ y, const float* __restrict__ B,
            const float* __restrict__ resid, float* __restrict__ out,
            const float* __restrict__ alpha_ptr) {
    constexpr int PX = H * H / NT;
    constexpr size_t PSTRIDE = (size_t)4 * 48 * H * H;
    constexpr int NW = NT / 32;
    __shared__ float sred[2 * NW + 2];
    __shared__ float s_plane[POOL ? H * H : 2];
    const int c = blockIdx.x, n = blockIdx.y, tid = threadIdx.x;
    const size_t base = ((size_t)n * 48 + c) * H * H;
    const float inv = 1.0f / (float)(H * H);
    const float b = B[c];

    float v[PX];
    float lsum = 0.f, lsq = 0.f;
    #pragma unroll
    for (int i = 0; i < PX; i++) {
        size_t idx = base + tid + i * NT;
        float t = b;
        #pragma unroll
        for (int p = 0; p < NPART; p++) t += y[p * PSTRIDE + idx];
        v[i] = t;
        lsum += t; lsq += t * t;
    }
    float m, va;
    blk_stats<NT>(lsum, lsq, sred, tid, inv, m, va);
    float rs = rsqrtf(va + EPSV);
    const float alpha = __ldg(alpha_ptr);

    lsum = 0.f; lsq = 0.f;
    #pragma unroll
    for (int i = 0; i < PX; i++) {
        float t = (v[i] - m) * rs;
        t = (t >= 0.f) ? t : alpha * t;
        v[i] = t;
        lsum += t; lsq += t * t;
    }

    if (!FULL) {
        #pragma unroll
        for (int i = 0; i < PX; i++) out[base + tid + i * NT] = v[i];
        return;
    }

    float m2, v2;
    blk_stats<NT>(lsum, lsq, sred, tid, inv, m2, v2);
    float rs2 = rsqrtf(v2 + EPSV);

    #pragma unroll
    for (int i = 0; i < PX; i++) {
        int px = tid + i * NT;
        float f = (v[i] - m2) * rs2 + resid[base + px];
        if (POOL) s_plane[px] = f;
        else      out[base + px] = f;
    }

    if (POOL) {
        __syncthreads();
        constexpr int HP = H / 2;
        const size_t ob = ((size_t)n * 48 + c) * HP * HP;
        #pragma unroll
        for (int j = 0; j < (HP * HP + NT - 1) / NT; j++) {
            int p = tid + j * NT;
            if (p < HP * HP) {
                int hh = p / HP, ww = p % HP;
                const float* q = &s_plane[(hh * 2) * H + ww * 2];
                out[ob + p] = fmaxf(fmaxf(q[0], q[1]), fmaxf(q[H], q[H + 1]));
            }
        }
    }
}

// ---------------- fused: bilinear-8x upsample + softmax + 3x3 reflect apply ----
// 2 px per thread in x (tile 32x16). skernel arrives as 2 split-K partials +
// bias. Pair-stage pipeline (2 channels/stage), 6 buffers.
__global__ void __launch_bounds__(256)
apply_fused(const float* __restrict__ x, const float* __restrict__ sk,
            const float* __restrict__ kb2, float* __restrict__ out) {
    constexpr int SROW = 36, BUFSZ = 18 * SROW;
    __shared__ float s_t[6][BUFSZ];

    const int n   = blockIdx.z;
    const int tid = threadIdx.x;
    const int txx = tid & 15, tyy = tid >> 4;
    const int w0 = blockIdx.x * 32, h0 = blockIdx.y * 16;
    const int h = h0 + tyy;
    const int wb = w0 + txx * 2;           // this thread's 2 px: wb, wb+1

    // per-pixel softmax kernels (bilinear, align corners: src = o*31/255)
    float fh = ((float)h * 31.0f) / 255.0f;
    int r0 = (int)floorf(fh);
    float fr = fh - (float)r0;
    int r1 = min(r0 + 1, 31);

    float kv[2][9];
    const float* skb = sk + (size_t)n * 9 * 1024;
    #pragma unroll
    for (int q = 0; q < 2; q++) {
        int w = wb + q;
        float fw = ((float)w * 31.0f) / 255.0f;
        int c0 = (int)floorf(fw);
        float fc = fw - (float)c0;
        int c1 = min(c0 + 1, 31);
        const float w00 = (1.f - fr) * (1.f - fc);
        const float w01 = (1.f - fr) * fc;
        const float w10 = fr * (1.f - fc);
        const float w11 = fr * fc;
        #pragma unroll
        for (int p = 0; p < 9; p++) {
            float a = 0.f;
            #pragma unroll
            for (int s = 0; s < 2; s++) {
                const float* sp = skb + (size_t)s * 4 * 9 * 1024 + p * 1024;
                a += w00 * __ldg(&sp[r0*32+c0]) + w01 * __ldg(&sp[r0*32+c1])
                   + w10 * __ldg(&sp[r1*32+c0]) + w11 * __ldg(&sp[r1*32+c1]);
            }
            kv[q][p] = a + __ldg(&kb2[p]);
        }
        float mx = kv[q][0];
        #pragma unroll
        for (int p = 1; p < 9; p++) mx = fmaxf(mx, kv[q][p]);
        float sum = 0.f;
        #pragma unroll
        for (int p = 0; p < 9; p++) { kv[q][p] = __expf(kv[q][p] - mx); sum += kv[q][p]; }
        float is = 1.0f / sum;
        #pragma unroll
        for (int p = 0; p < 9; p++) kv[q][p] *= is;
    }

    // precompute reflect-padded load slots (18x34 = 612 elems, <=3 per thread)
    int goff[3], soff[3]; bool act[3];
    #pragma unroll
    for (int j = 0; j < 3; j++) {
        int e = tid + j * 256;
        act[j] = (e < 612);
        int r = e / 34, cc = e - r * 34;
        int gr = h0 + r - 1; gr = gr < 0 ? -gr : (gr > 255 ? 510 - gr : gr);
        int gc = w0 + cc - 1; gc = gc < 0 ? -gc : (gc > 255 ? 510 - gc : gc);
        goff[j] = act[j] ? gr * 256 + gc : 0;
        soff[j] = act[j] ? r * SROW + cc : 0;
    }
    uint32_t sb[6];
    #pragma unroll
    for (int b = 0; b < 6; b++) sb[b] = s2u(s_t[b]);

    const float* xb = x + (size_t)n * 48 * 65536;
    float* ob = out + (size_t)n * 48 * 65536 + (size_t)h * 256 + wb;

    auto ldch = [&](int c, int b) {
        const float* xc = xb + (size_t)c * 65536;
        #pragma unroll
        for (int j = 0; j < 3; j++)
            if (act[j]) cp4(sb[b] + (uint32_t)soff[j] * 4, xc + goff[j]);
    };

    ldch(0, 0);
    ldch(1, 1);
    CP_COMMIT();          // pair 0

    for (int p = 0; p < 24; p++) {
        const int c = 2 * p;
        const int nb = ((p + 1) % 3) * 2;
        if (c + 2 < 48) { ldch(c + 2, nb); ldch(c + 3, nb + 1); }
        CP_COMMIT();
        CP_WAIT1();
        __syncthreads();
        const int cb = (p % 3) * 2;
        #pragma unroll
        for (int qch = 0; qch < 2; qch++) {
            const float* buf = s_t[cb + qch];
            float s0 = 0.f, s1 = 0.f;
            #pragma unroll
            for (int dy = 0; dy < 3; dy++) {
                const float* rp = &buf[(tyy + dy) * SROW + txx * 2];
                float r[4] = { rp[0], rp[1], rp[2], rp[3] };
                #pragma unroll
                for (int dx = 0; dx < 3; dx++) {
                    s0 = fmaf(kv[0][dy * 3 + dx], r[dx],     s0);
                    s1 = fmaf(kv[1][dy * 3 + dx], r[dx + 1], s1);
                }
            }
            *(float2*)&ob[(size_t)(c + qch) * 65536] = make_float2(s0, s1);
        }
    }
}

// ---------------- host launcher ----------------
extern "C" void kernel_launch(void* const* d_in, const int* in_sizes, int n_in,
                              void* d_out, int out_size) {
    const float* x   = (const float*)d_in[0];
    const float* x_  = (const float*)d_in[1];
    const float* p1w = (const float*)d_in[2];
    const float* p1b = (const float*)d_in[3];
    const float* p1a = (const float*)d_in[4];
    const float* p2w = (const float*)d_in[5];
    const float* p2b = (const float*)d_in[6];
    const float* p2a = (const float*)d_in[7];
    const float* kw1 = (const float*)d_in[8];
    const float* kb1 = (const float*)d_in[9];
    const float* ka  = (const float*)d_in[10];
    const float* kw2 = (const float*)d_in[11];
    const float* kb2 = (const float*)d_in[12];
    float* out = (float*)d_out;

    float *ga, *gb, *gc, *gd, *gp64, *gp32, *gskp;
    cudaGetSymbolAddress((void**)&ga,   g_a);
    cudaGetSymbolAddress((void**)&gb,   g_b);
    cudaGetSymbolAddress((void**)&gc,   g_c);
    cudaGetSymbolAddress((void**)&gd,   g_d);
    cudaGetSymbolAddress((void**)&gp64, g_p64);
    cudaGetSymbolAddress((void**)&gp32, g_p32);
    cudaGetSymbolAddress((void**)&gskp, g_skp);

    const size_t WS = (size_t)48 * 48 * 9;
    const dim3 g64(4, 6, 32);     // 4 row-tiles, 6 cout-groups (KO=8), n*split8
    const dim3 g32(2, 6, 32);     // 2 row-tiles, 6 groups (KO=8), n*split8
    const dim3 gnorm(48, 4);

    // x1 = x_[:, :, ::4, ::4]
    down_kernel<<<(4*48*64*64 + 255) / 256, 256>>>(x_, ga);

    // 3 basic blocks @ 64x64 (split8 partials; merge+bias+resid in norm)
    conv_fast<64, 4, 48, 8, 8><<<g64, 256>>>(ga, gp64, p1w + 0 * WS);
    norm_kernel<64, 1024, true, 8, false><<<gnorm, 1024>>>(gp64, p1b + 0,  ga, gb, p1a + 0);
    conv_fast<64, 4, 48, 8, 8><<<g64, 256>>>(gb, gp64, p1w + 1 * WS);
    norm_kernel<64, 1024, true, 8, false><<<gnorm, 1024>>>(gp64, p1b + 48, gb, ga, p1a + 1);
    conv_fast<64, 4, 48, 8, 8><<<g64, 256>>>(ga, gp64, p1w + 2 * WS);
    // block-3 tail + fused 2x2 maxpool -> gc (32^2)
    norm_kernel<64, 1024, true, 8, true><<<gnorm, 1024>>>(gp64, p1b + 96, ga, gc, p1a + 2);

    // 3 basic blocks @ 32x32 (8-way ci-split, merged in norm)
    conv_fast<32, 2, 48, 8, 8><<<g32, 256>>>(gc, gp32, p2w + 0 * WS);
    norm_kernel<32, 256, true, 8, false><<<gnorm, 256>>>(gp32, p2b + 0,  gc, gd, p2a + 0);
    conv_fast<32, 2, 48, 8, 8><<<g32, 256>>>(gd, gp32, p2w + 1 * WS);
    norm_kernel<32, 256, true, 8, false><<<gnorm, 256>>>(gp32, p2b + 48, gd, gc, p2a + 1);
    conv_fast<32, 2, 48, 8, 8><<<g32, 256>>>(gc, gp32, p2w + 2 * WS);
    norm_kernel<32, 256, true, 8, false><<<gnorm, 256>>>(gp32, p2b + 96, gc, gd, p2a + 2);

    // head: conv + inorm + prelu
    conv_fast<32, 2, 48, 8, 8><<<g32, 256>>>(gd, gp32, kw1);
    norm_kernel<32, 256, false, 8, false><<<gnorm, 256>>>(gp32, kb1, nullptr, gc, ka);

    // skernel conv (9 couts, 2 split-K partials; bias added in apply)
    conv_fast<32, 2, 9, 3, 2><<<dim3(2, 3, 8), 256>>>(gc, gskp, kw2);

    // fused upsample + softmax + adaptive 3x3 apply (2 px/thread)
    apply_fused<<<dim3(8, 16, 4), 256>>>(x, gskp, kb2, out);
}